// round 2
// baseline (speedup 1.0000x reference)
#include <cuda_runtime.h>
#include <math.h>

#define IMG_H 512
#define IMG_W 512
#define NB    64
#define NPIX  (IMG_H * IMG_W)
#define NPEL  (NPIX * 3)
#define RBLK  32

__device__ float g_partial0[NB * RBLK];
__device__ float g_partial1[NB * RBLK];
__device__ float g_mean0[NB];
__device__ float g_mean1[NB];

struct F3 { float x, y, z; };

struct LayerP {
    int   op;
    float f;                    // pointwise enhancement factor
    float a, b, tx, c, d, ty;   // inverse affine
    float m;                    // mean (contrast)
};

__device__ __forceinline__ void setup_params(LayerP& P, int op, float s, float mean)
{
    P.op = op; P.m = mean;
    P.a = 1.f; P.b = 0.f; P.tx = 0.f; P.c = 0.f; P.d = 1.f; P.ty = 0.f;
    if (op == 0) {                          // rotate s*15deg
        float th = s * 0.2617993877991494f;
        P.a = cosf(th); P.b = sinf(th); P.c = -P.b; P.d = P.a;
    } else if (op == 1) { P.b  = -s * 0.15f; }                 // shear_x
    else if (op == 2)   { P.c  = -s * 0.15f; }                 // shear_y
    else if (op == 3)   { P.tx = -s * 0.15f * (float)IMG_W; }  // trans_x
    else if (op == 4)   { P.ty = -s * 0.15f * (float)IMG_H; }  // trans_y
    P.f = (s > 0.f) ? 1.45f : (1.0f / 1.45f);   // ENH = 1+0.9*0.5
}

// one bilinear corner tap with reference fill semantics
__device__ __forceinline__ void gather_acc(const float* __restrict__ img,
                                           float yy, float xx, float w, F3& r)
{
    bool valid = (xx >= 0.f) && (xx <= (float)(IMG_W - 1)) &&
                 (yy >= 0.f) && (yy <= (float)(IMG_H - 1));
    int xc = (int)fminf(fmaxf(xx, 0.f), (float)(IMG_W - 1));
    int yc = (int)fminf(fmaxf(yy, 0.f), (float)(IMG_H - 1));
    const float* p = img + ((size_t)yc * IMG_W + xc) * 3;
    if (valid) { r.x += w * p[0]; r.y += w * p[1]; r.z += w * p[2]; }
    else       { float f = w * 0.5f; r.x += f; r.y += f; r.z += f; }
}

// value of the layer-0 intermediate at integer pixel (x,y), x,y in-bounds
__device__ __forceinline__ F3 eval0(const float* __restrict__ img,
                                    const LayerP& P, int x, int y)
{
    F3 r;
    if (P.op < 5) {
        const float cx = (IMG_W - 1) * 0.5f, cy = (IMG_H - 1) * 0.5f;
        float xf = (float)x - cx, yf = (float)y - cy;
        float xi = P.a * xf + P.b * yf + P.tx + cx;
        float yi = P.c * xf + P.d * yf + P.ty + cy;
        float x0 = floorf(xi), y0 = floorf(yi);
        float wx = xi - x0,    wy = yi - y0;
        r.x = r.y = r.z = 0.f;
        gather_acc(img, y0,       x0,       (1.f - wx) * (1.f - wy), r);
        gather_acc(img, y0,       x0 + 1.f, wx         * (1.f - wy), r);
        gather_acc(img, y0 + 1.f, x0,       (1.f - wx) * wy,         r);
        gather_acc(img, y0 + 1.f, x0 + 1.f, wx         * wy,         r);
        return r;                     // affine: no clip
    }
    const float* p = img + ((size_t)y * IMG_W + x) * 3;
    float v0 = p[0], v1 = p[1], v2 = p[2];
    if (P.op == 5) {                              // brightness
        r.x = P.f * v0; r.y = P.f * v1; r.z = P.f * v2;
    } else if (P.op == 6) {                       // contrast
        r.x = P.m + P.f * (v0 - P.m);
        r.y = P.m + P.f * (v1 - P.m);
        r.z = P.m + P.f * (v2 - P.m);
    } else {                                      // sharpness
        float s0 = 0.f, s1 = 0.f, s2 = 0.f;
        #pragma unroll
        for (int dy = -1; dy <= 1; dy++) {
            int yy = min(max(y + dy, 0), IMG_H - 1);
            #pragma unroll
            for (int dx = -1; dx <= 1; dx++) {
                int xx = min(max(x + dx, 0), IMG_W - 1);
                float k = (dx == 0 && dy == 0) ? (5.0f/13.0f) : (1.0f/13.0f);
                const float* q = img + ((size_t)yy * IMG_W + xx) * 3;
                s0 += k * q[0]; s1 += k * q[1]; s2 += k * q[2];
            }
        }
        r.x = s0 + P.f * (v0 - s0);
        r.y = s1 + P.f * (v1 - s1);
        r.z = s2 + P.f * (v2 - s2);
    }
    r.x = fminf(fmaxf(r.x, 0.f), 1.f);
    r.y = fminf(fmaxf(r.y, 0.f), 1.f);
    r.z = fminf(fmaxf(r.z, 0.f), 1.f);
    return r;
}

// ---------------------------------------------------------------------------
// reduce0: mean of original (only images with op0 == contrast), float4 loads
// ---------------------------------------------------------------------------
__global__ void reduce0_kernel(const float* __restrict__ in,
                               const int* __restrict__ op_ids)
{
    int b = blockIdx.y;
    if (op_ids[b * 2] != 6) return;
    const float4* img = (const float4*)(in + (size_t)b * NPEL);
    float s = 0.f;
    for (int i = blockIdx.x * 256 + threadIdx.x; i < NPEL / 4; i += RBLK * 256) {
        float4 v = img[i];
        s += v.x + v.y + v.z + v.w;
    }
    __shared__ float sd[256];
    sd[threadIdx.x] = s;
    __syncthreads();
    #pragma unroll
    for (int st = 128; st > 0; st >>= 1) {
        if (threadIdx.x < st) sd[threadIdx.x] += sd[threadIdx.x + st];
        __syncthreads();
    }
    if (threadIdx.x == 0) g_partial0[b * RBLK + blockIdx.x] = sd[0];
}

__global__ void finalize0_kernel(const int* __restrict__ op_ids)
{
    int b = threadIdx.x;
    if (b >= NB || op_ids[b * 2] != 6) return;
    float s = 0.f;
    #pragma unroll
    for (int i = 0; i < RBLK; i++) s += g_partial0[b * RBLK + i];
    g_mean0[b] = s * (1.0f / (float)NPEL);
}

// ---------------------------------------------------------------------------
// reduce1: mean of the (virtual) intermediate — only images with op1==contrast
// ---------------------------------------------------------------------------
__global__ void reduce1_kernel(const float* __restrict__ in,
                               const int* __restrict__ op_ids,
                               const int* __restrict__ signs)
{
    int b = blockIdx.y;
    if (op_ids[b * 2 + 1] != 6) return;
    LayerP P0;
    setup_params(P0, op_ids[b * 2], signs[b * 2] ? 1.f : -1.f, g_mean0[b]);
    const float* img = in + (size_t)b * NPEL;
    float s = 0.f;
    for (int i = blockIdx.x * 256 + threadIdx.x; i < NPIX; i += RBLK * 256) {
        F3 v = eval0(img, P0, i & (IMG_W - 1), i >> 9);
        s += v.x + v.y + v.z;
    }
    __shared__ float sd[256];
    sd[threadIdx.x] = s;
    __syncthreads();
    #pragma unroll
    for (int st = 128; st > 0; st >>= 1) {
        if (threadIdx.x < st) sd[threadIdx.x] += sd[threadIdx.x + st];
        __syncthreads();
    }
    if (threadIdx.x == 0) g_partial1[b * RBLK + blockIdx.x] = sd[0];
}

__global__ void finalize1_kernel(const int* __restrict__ op_ids)
{
    int b = threadIdx.x;
    if (b >= NB || op_ids[b * 2 + 1] != 6) return;
    float s = 0.f;
    #pragma unroll
    for (int i = 0; i < RBLK; i++) s += g_partial1[b * RBLK + i];
    g_mean1[b] = s * (1.0f / (float)NPEL);
}

// ---------------------------------------------------------------------------
// Fused: both layers in one pass (read original once, write output once).
// ---------------------------------------------------------------------------
__global__ void fused_kernel(const float* __restrict__ in,
                             float* __restrict__ out,
                             const int* __restrict__ op_ids,
                             const int* __restrict__ signs)
{
    const int b   = blockIdx.z;
    const int idx = blockIdx.x * blockDim.x + threadIdx.x;
    const int y   = idx >> 9;
    const int x   = idx & (IMG_W - 1);

    const float* img = in + (size_t)b * NPEL;
    float* o = out + (size_t)b * NPEL + (size_t)idx * 3;

    LayerP P0, P1;
    setup_params(P0, op_ids[b * 2],     signs[b * 2]     ? 1.f : -1.f, g_mean0[b]);
    setup_params(P1, op_ids[b * 2 + 1], signs[b * 2 + 1] ? 1.f : -1.f, g_mean1[b]);

    F3 r;
    if (P1.op < 5) {
        // layer-1 affine: 4 corners on the virtual intermediate
        const float cx = (IMG_W - 1) * 0.5f, cy = (IMG_H - 1) * 0.5f;
        float xf = (float)x - cx, yf = (float)y - cy;
        float xi = P1.a * xf + P1.b * yf + P1.tx + cx;
        float yi = P1.c * xf + P1.d * yf + P1.ty + cy;
        float x0 = floorf(xi), y0 = floorf(yi);
        float wx = xi - x0,    wy = yi - y0;
        float w[4]  = { (1.f-wx)*(1.f-wy), wx*(1.f-wy), (1.f-wx)*wy, wx*wy };
        float qx[4] = { x0, x0 + 1.f, x0,       x0 + 1.f };
        float qy[4] = { y0, y0,       y0 + 1.f, y0 + 1.f };
        r.x = r.y = r.z = 0.f;
        #pragma unroll
        for (int i = 0; i < 4; i++) {
            bool valid = (qx[i] >= 0.f) && (qx[i] <= (float)(IMG_W - 1)) &&
                         (qy[i] >= 0.f) && (qy[i] <= (float)(IMG_H - 1));
            if (valid) {
                F3 v = eval0(img, P0, (int)qx[i], (int)qy[i]);
                r.x += w[i] * v.x; r.y += w[i] * v.y; r.z += w[i] * v.z;
            } else {
                float f = w[i] * 0.5f;
                r.x += f; r.y += f; r.z += f;
            }
        }
        // affine: no clip
    } else if (P1.op == 5) {                 // brightness
        F3 v = eval0(img, P0, x, y);
        r.x = P1.f * v.x; r.y = P1.f * v.y; r.z = P1.f * v.z;
        r.x = fminf(fmaxf(r.x, 0.f), 1.f);
        r.y = fminf(fmaxf(r.y, 0.f), 1.f);
        r.z = fminf(fmaxf(r.z, 0.f), 1.f);
    } else if (P1.op == 6) {                 // contrast
        F3 v = eval0(img, P0, x, y);
        float m = P1.m;
        r.x = fminf(fmaxf(m + P1.f * (v.x - m), 0.f), 1.f);
        r.y = fminf(fmaxf(m + P1.f * (v.y - m), 0.f), 1.f);
        r.z = fminf(fmaxf(m + P1.f * (v.z - m), 0.f), 1.f);
    } else {                                 // sharpness on intermediate
        F3 sm = {0.f, 0.f, 0.f}, ctr = {0.f, 0.f, 0.f};
        #pragma unroll
        for (int dy = -1; dy <= 1; dy++) {
            int yy = min(max(y + dy, 0), IMG_H - 1);
            #pragma unroll
            for (int dx = -1; dx <= 1; dx++) {
                int xx = min(max(x + dx, 0), IMG_W - 1);
                float k = (dx == 0 && dy == 0) ? (5.0f/13.0f) : (1.0f/13.0f);
                F3 v = eval0(img, P0, xx, yy);
                if (dx == 0 && dy == 0) ctr = v;
                sm.x += k * v.x; sm.y += k * v.y; sm.z += k * v.z;
            }
        }
        r.x = fminf(fmaxf(sm.x + P1.f * (ctr.x - sm.x), 0.f), 1.f);
        r.y = fminf(fmaxf(sm.y + P1.f * (ctr.y - sm.y), 0.f), 1.f);
        r.z = fminf(fmaxf(sm.z + P1.f * (ctr.z - sm.z), 0.f), 1.f);
    }

    o[0] = r.x; o[1] = r.y; o[2] = r.z;
}

// ---------------------------------------------------------------------------
extern "C" void kernel_launch(void* const* d_in, const int* in_sizes, int n_in,
                              void* d_out, int out_size)
{
    const float* images = (const float*)d_in[0];
    const int*   op_ids = (const int*)  d_in[1];
    const int*   signs  = (const int*)  d_in[2];
    float*       out    = (float*)d_out;

    dim3 rgrid(RBLK, NB);
    dim3 agrid(NPIX / 256, 1, NB);

    reduce0_kernel  <<<rgrid, 256>>>(images, op_ids);
    finalize0_kernel<<<1, 64>>>(op_ids);
    reduce1_kernel  <<<rgrid, 256>>>(images, op_ids, signs);
    finalize1_kernel<<<1, 64>>>(op_ids);
    fused_kernel    <<<agrid, 256>>>(images, out, op_ids, signs);
}

// round 3
// speedup vs baseline: 1.9853x; 1.9853x over previous
#include <cuda_runtime.h>
#include <math.h>

#define IMG_H 512
#define IMG_W 512
#define NB    64
#define NPIX  (IMG_H * IMG_W)
#define NPEL  (NPIX * 3)
#define RBLK  32

__device__ float g_scratch[(size_t)NB * NPEL];   // intermediate for non-fused images
__device__ float g_partial0[NB * RBLK];
__device__ float g_partial1[NB * RBLK];
__device__ float g_mean0[NB];
__device__ float g_mean1[NB];

struct F3 { float x, y, z; };

struct LayerP {
    int   op;
    float f;                    // pointwise enhancement factor
    float a, b, tx, c, d, ty;   // inverse affine
    float m;                    // mean (contrast)
};

__device__ __forceinline__ void setup_params(LayerP& P, int op, float s, float mean)
{
    P.op = op; P.m = mean;
    P.a = 1.f; P.b = 0.f; P.tx = 0.f; P.c = 0.f; P.d = 1.f; P.ty = 0.f;
    if (op == 0) {                          // rotate s*15deg
        float th = s * 0.2617993877991494f;
        P.a = cosf(th); P.b = sinf(th); P.c = -P.b; P.d = P.a;
    } else if (op == 1) { P.b  = -s * 0.15f; }
    else if (op == 2)   { P.c  = -s * 0.15f; }
    else if (op == 3)   { P.tx = -s * 0.15f * (float)IMG_W; }
    else if (op == 4)   { P.ty = -s * 0.15f * (float)IMG_H; }
    P.f = (s > 0.f) ? 1.45f : (1.0f / 1.45f);   // ENH = 1 + 0.9*0.5
}

__device__ __forceinline__ void gather_acc(const float* __restrict__ img,
                                           float yy, float xx, float w, F3& r)
{
    bool valid = (xx >= 0.f) && (xx <= (float)(IMG_W - 1)) &&
                 (yy >= 0.f) && (yy <= (float)(IMG_H - 1));
    int xc = (int)fminf(fmaxf(xx, 0.f), (float)(IMG_W - 1));
    int yc = (int)fminf(fmaxf(yy, 0.f), (float)(IMG_H - 1));
    const float* p = img + ((size_t)yc * IMG_W + xc) * 3;
    if (valid) { r.x += w * p[0]; r.y += w * p[1]; r.z += w * p[2]; }
    else       { float f = w * 0.5f; r.x += f; r.y += f; r.z += f; }
}

__device__ __forceinline__ F3 bilin(const float* __restrict__ img,
                                    const LayerP& P, int x, int y)
{
    const float cx = (IMG_W - 1) * 0.5f, cy = (IMG_H - 1) * 0.5f;
    float xf = (float)x - cx, yf = (float)y - cy;
    float xi = P.a * xf + P.b * yf + P.tx + cx;
    float yi = P.c * xf + P.d * yf + P.ty + cy;
    float x0 = floorf(xi), y0 = floorf(yi);
    float wx = xi - x0,    wy = yi - y0;
    F3 r; r.x = r.y = r.z = 0.f;
    gather_acc(img, y0,       x0,       (1.f - wx) * (1.f - wy), r);
    gather_acc(img, y0,       x0 + 1.f, wx         * (1.f - wy), r);
    gather_acc(img, y0 + 1.f, x0,       (1.f - wx) * wy,         r);
    gather_acc(img, y0 + 1.f, x0 + 1.f, wx         * wy,         r);
    return r;   // affine: no clip
}

// scalar intermediate value (used only by reduce1 recompute path)
__device__ __forceinline__ F3 eval0(const float* __restrict__ img,
                                    const LayerP& P, int x, int y)
{
    if (P.op < 5) return bilin(img, P, x, y);
    const float* p = img + ((size_t)y * IMG_W + x) * 3;
    F3 r;
    float v0 = p[0], v1 = p[1], v2 = p[2];
    if (P.op == 5) {
        r.x = P.f * v0; r.y = P.f * v1; r.z = P.f * v2;
    } else if (P.op == 6) {
        r.x = P.m + P.f * (v0 - P.m);
        r.y = P.m + P.f * (v1 - P.m);
        r.z = P.m + P.f * (v2 - P.m);
    } else {
        float s0 = 0.f, s1 = 0.f, s2 = 0.f;
        #pragma unroll
        for (int dy = -1; dy <= 1; dy++) {
            int yy = min(max(y + dy, 0), IMG_H - 1);
            #pragma unroll
            for (int dx = -1; dx <= 1; dx++) {
                int xx = min(max(x + dx, 0), IMG_W - 1);
                float k = (dx == 0 && dy == 0) ? (5.0f/13.0f) : (1.0f/13.0f);
                const float* q = img + ((size_t)yy * IMG_W + xx) * 3;
                s0 += k * q[0]; s1 += k * q[1]; s2 += k * q[2];
            }
        }
        r.x = s0 + P.f * (v0 - s0);
        r.y = s1 + P.f * (v1 - s1);
        r.z = s2 + P.f * (v2 - s2);
    }
    r.x = fminf(fmaxf(r.x, 0.f), 1.f);
    r.y = fminf(fmaxf(r.y, 0.f), 1.f);
    r.z = fminf(fmaxf(r.z, 0.f), 1.f);
    return r;
}

// ---------------------------------------------------------------------------
// Quad (4 consecutive pixels, same row) evaluation of one layer.
// v[12] = pixel-major {r,g,b} x 4. x is a multiple of 4.
// ---------------------------------------------------------------------------
__device__ __forceinline__ void layer_quad(const float* __restrict__ img,
                                           const LayerP& P, int x, int y,
                                           float v[12])
{
    if (P.op < 5) {
        #pragma unroll
        for (int i = 0; i < 4; i++) {
            F3 r = bilin(img, P, x + i, y);
            v[i*3] = r.x; v[i*3+1] = r.y; v[i*3+2] = r.z;
        }
        return;   // no clip
    }
    if (P.op == 7) {
        // sharpness via per-channel column sums over 6 columns x 3 rows
        const int ym = max(y - 1, 0), yp = min(y + 1, IMG_H - 1);
        float ctr[12], sm[12];
        #pragma unroll
        for (int ch = 0; ch < 3; ch++) {
            float cs[6];
            #pragma unroll
            for (int j = 0; j < 6; j++) {
                int xx = min(max(x - 1 + j, 0), IMG_W - 1);
                float vm = img[((size_t)ym * IMG_W + xx) * 3 + ch];
                float vc = img[((size_t)y  * IMG_W + xx) * 3 + ch];
                float vp = img[((size_t)yp * IMG_W + xx) * 3 + ch];
                cs[j] = vm + vc + vp;
                if (j >= 1 && j <= 4) ctr[(j-1)*3 + ch] = vc;
            }
            #pragma unroll
            for (int i = 0; i < 4; i++)
                sm[i*3+ch] = (cs[i] + cs[i+1] + cs[i+2] + 4.f * ctr[i*3+ch]) * (1.f/13.f);
        }
        #pragma unroll
        for (int k = 0; k < 12; k++)
            v[k] = fminf(fmaxf(sm[k] + P.f * (ctr[k] - sm[k]), 0.f), 1.f);
        return;
    }
    // brightness / contrast: fully vectorized
    const float4* s4 = (const float4*)(img + (size_t)(y * IMG_W + x) * 3);
    float4 a0 = s4[0], a1 = s4[1], a2 = s4[2];
    float t[12] = { a0.x,a0.y,a0.z,a0.w, a1.x,a1.y,a1.z,a1.w, a2.x,a2.y,a2.z,a2.w };
    if (P.op == 5) {
        #pragma unroll
        for (int k = 0; k < 12; k++)
            v[k] = fminf(fmaxf(P.f * t[k], 0.f), 1.f);
    } else {
        float m = P.m;
        #pragma unroll
        for (int k = 0; k < 12; k++)
            v[k] = fminf(fmaxf(m + P.f * (t[k] - m), 0.f), 1.f);
    }
}

// ---------------------------------------------------------------------------
// reduce0: mean of original images whose op0 == contrast
// ---------------------------------------------------------------------------
__global__ void reduce0_kernel(const float* __restrict__ in,
                               const int* __restrict__ op_ids)
{
    int b = blockIdx.y;
    if (op_ids[b * 2] != 6) return;
    const float4* img = (const float4*)(in + (size_t)b * NPEL);
    float s = 0.f;
    for (int i = blockIdx.x * 256 + threadIdx.x; i < NPEL / 4; i += RBLK * 256) {
        float4 v = img[i];
        s += v.x + v.y + v.z + v.w;
    }
    __shared__ float sd[256];
    sd[threadIdx.x] = s;
    __syncthreads();
    #pragma unroll
    for (int st = 128; st > 0; st >>= 1) {
        if (threadIdx.x < st) sd[threadIdx.x] += sd[threadIdx.x + st];
        __syncthreads();
    }
    if (threadIdx.x == 0) g_partial0[b * RBLK + blockIdx.x] = sd[0];
}

__global__ void finalize0_kernel(const int* __restrict__ op_ids)
{
    int b = threadIdx.x;
    if (b >= NB || op_ids[b * 2] != 6) return;
    float s = 0.f;
    #pragma unroll
    for (int i = 0; i < RBLK; i++) s += g_partial0[b * RBLK + i];
    g_mean0[b] = s * (1.0f / (float)NPEL);
}

// ---------------------------------------------------------------------------
// reduce1: mean of the virtual intermediate, recomputed — only op1==contrast
// (these are fused-path images; their intermediate is never materialized)
// ---------------------------------------------------------------------------
__global__ void reduce1_kernel(const float* __restrict__ in,
                               const int* __restrict__ op_ids,
                               const int* __restrict__ signs)
{
    int b = blockIdx.y;
    if (op_ids[b * 2 + 1] != 6) return;
    LayerP P0;
    setup_params(P0, op_ids[b * 2], signs[b * 2] ? 1.f : -1.f, g_mean0[b]);
    const float* img = in + (size_t)b * NPEL;
    float s = 0.f;
    for (int i = blockIdx.x * 256 + threadIdx.x; i < NPIX; i += RBLK * 256) {
        F3 v = eval0(img, P0, i & (IMG_W - 1), i >> 9);
        s += v.x + v.y + v.z;
    }
    __shared__ float sd[256];
    sd[threadIdx.x] = s;
    __syncthreads();
    #pragma unroll
    for (int st = 128; st > 0; st >>= 1) {
        if (threadIdx.x < st) sd[threadIdx.x] += sd[threadIdx.x + st];
        __syncthreads();
    }
    if (threadIdx.x == 0) g_partial1[b * RBLK + blockIdx.x] = sd[0];
}

__global__ void finalize1_kernel(const int* __restrict__ op_ids)
{
    int b = threadIdx.x;
    if (b >= NB || op_ids[b * 2 + 1] != 6) return;
    float s = 0.f;
    #pragma unroll
    for (int i = 0; i < RBLK; i++) s += g_partial1[b * RBLK + i];
    g_mean1[b] = s * (1.0f / (float)NPEL);
}

// ---------------------------------------------------------------------------
// pass1: layer 0 for all images. If op1 is pointwise (brightness/contrast),
// apply it immediately and write the FINAL result to out (fused path).
// Otherwise write the intermediate to scratch.
// ---------------------------------------------------------------------------
__global__ void pass1_kernel(const float* __restrict__ in,
                             float* __restrict__ out,
                             const int* __restrict__ op_ids,
                             const int* __restrict__ signs)
{
    const int b  = blockIdx.z;
    const int t  = blockIdx.x * blockDim.x + threadIdx.x;   // quad index
    const int p0 = t * 4;
    const int y  = p0 >> 9;
    const int x  = p0 & (IMG_W - 1);

    const float* img = in + (size_t)b * NPEL;
    const int op0 = op_ids[b * 2], op1 = op_ids[b * 2 + 1];
    const float s0 = signs[b * 2]     ? 1.f : -1.f;
    const float s1 = signs[b * 2 + 1] ? 1.f : -1.f;
    const bool fused = (op1 == 5) || (op1 == 6);

    LayerP P0;
    setup_params(P0, op0, s0, g_mean0[b]);

    float v[12];
    layer_quad(img, P0, x, y, v);

    if (fused) {
        const float f1 = (s1 > 0.f) ? 1.45f : (1.0f / 1.45f);
        if (op1 == 5) {
            #pragma unroll
            for (int k = 0; k < 12; k++)
                v[k] = fminf(fmaxf(f1 * v[k], 0.f), 1.f);
        } else {
            const float m = g_mean1[b];
            #pragma unroll
            for (int k = 0; k < 12; k++)
                v[k] = fminf(fmaxf(m + f1 * (v[k] - m), 0.f), 1.f);
        }
    }

    float* dst = (fused ? out : g_scratch) + (size_t)b * NPEL + (size_t)p0 * 3;
    float4* d4 = (float4*)dst;
    d4[0] = make_float4(v[0], v[1], v[2],  v[3]);
    d4[1] = make_float4(v[4], v[5], v[6],  v[7]);
    d4[2] = make_float4(v[8], v[9], v[10], v[11]);
}

// ---------------------------------------------------------------------------
// pass2: layer 1 (affine or sharpness only) from scratch -> out.
// Fused images exit immediately.
// ---------------------------------------------------------------------------
__global__ void pass2_kernel(float* __restrict__ out,
                             const int* __restrict__ op_ids,
                             const int* __restrict__ signs)
{
    const int b   = blockIdx.z;
    const int op1 = op_ids[b * 2 + 1];
    if (op1 == 5 || op1 == 6) return;       // already written by pass1

    const int t  = blockIdx.x * blockDim.x + threadIdx.x;
    const int p0 = t * 4;
    const int y  = p0 >> 9;
    const int x  = p0 & (IMG_W - 1);

    const float* img = g_scratch + (size_t)b * NPEL;
    const float s1 = signs[b * 2 + 1] ? 1.f : -1.f;

    LayerP P1;
    setup_params(P1, op1, s1, 0.f);         // contrast impossible here

    float v[12];
    layer_quad(img, P1, x, y, v);

    float4* d4 = (float4*)(out + (size_t)b * NPEL + (size_t)p0 * 3);
    d4[0] = make_float4(v[0], v[1], v[2],  v[3]);
    d4[1] = make_float4(v[4], v[5], v[6],  v[7]);
    d4[2] = make_float4(v[8], v[9], v[10], v[11]);
}

// ---------------------------------------------------------------------------
extern "C" void kernel_launch(void* const* d_in, const int* in_sizes, int n_in,
                              void* d_out, int out_size)
{
    const float* images = (const float*)d_in[0];
    const int*   op_ids = (const int*)  d_in[1];
    const int*   signs  = (const int*)  d_in[2];
    float*       out    = (float*)d_out;

    dim3 rgrid(RBLK, NB);
    dim3 qgrid(NPIX / 4 / 256, 1, NB);

    reduce0_kernel  <<<rgrid, 256>>>(images, op_ids);
    finalize0_kernel<<<1, 64>>>(op_ids);
    reduce1_kernel  <<<rgrid, 256>>>(images, op_ids, signs);
    finalize1_kernel<<<1, 64>>>(op_ids);
    pass1_kernel    <<<qgrid, 256>>>(images, out, op_ids, signs);
    pass2_kernel    <<<qgrid, 256>>>(out, op_ids, signs);
}

// round 4
// speedup vs baseline: 2.1757x; 1.0959x over previous
#include <cuda_runtime.h>
#include <math.h>

#define IMG_H 512
#define IMG_W 512
#define NB    64
#define NPIX  (IMG_H * IMG_W)
#define NPEL  (NPIX * 3)
#define RBLK  32

__device__ float g_scratch[(size_t)NB * NPEL];
__device__ float g_partial0[NB * RBLK];
__device__ float g_partial1[NB * RBLK];
__device__ float g_mean0[NB];
__device__ float g_mean1[NB];

struct F3 { float x, y, z; };

struct LayerP {
    int   op;
    float f;
    float a, b, tx, c, d, ty;
    float m;
};

__device__ __forceinline__ void setup_params(LayerP& P, int op, float s, float mean)
{
    P.op = op; P.m = mean;
    P.a = 1.f; P.b = 0.f; P.tx = 0.f; P.c = 0.f; P.d = 1.f; P.ty = 0.f;
    if (op == 0) {                          // rotate s*15deg
        float th = s * 0.2617993877991494f;
        P.a = cosf(th); P.b = sinf(th); P.c = -P.b; P.d = P.a;
    } else if (op == 1) { P.b  = -s * 0.15f; }
    else if (op == 2)   { P.c  = -s * 0.15f; }
    else if (op == 3)   { P.tx = -s * 0.15f * (float)IMG_W; }
    else if (op == 4)   { P.ty = -s * 0.15f * (float)IMG_H; }
    P.f = (s > 0.f) ? 1.45f : (1.0f / 1.45f);   // ENH = 1 + 0.9*0.5
}

__device__ __forceinline__ void gather_acc(const float* __restrict__ img,
                                           float yy, float xx, float w, F3& r)
{
    bool valid = (xx >= 0.f) && (xx <= (float)(IMG_W - 1)) &&
                 (yy >= 0.f) && (yy <= (float)(IMG_H - 1));
    int xc = (int)fminf(fmaxf(xx, 0.f), (float)(IMG_W - 1));
    int yc = (int)fminf(fmaxf(yy, 0.f), (float)(IMG_H - 1));
    const float* p = img + ((size_t)yc * IMG_W + xc) * 3;
    if (valid) { r.x += w * p[0]; r.y += w * p[1]; r.z += w * p[2]; }
    else       { float f = w * 0.5f; r.x += f; r.y += f; r.z += f; }
}

__device__ __forceinline__ F3 bilin(const float* __restrict__ img,
                                    const LayerP& P, int x, int y)
{
    const float cx = (IMG_W - 1) * 0.5f, cy = (IMG_H - 1) * 0.5f;
    float xf = (float)x - cx, yf = (float)y - cy;
    float xi = P.a * xf + P.b * yf + P.tx + cx;
    float yi = P.c * xf + P.d * yf + P.ty + cy;
    float x0 = floorf(xi), y0 = floorf(yi);
    float wx = xi - x0,    wy = yi - y0;
    F3 r; r.x = r.y = r.z = 0.f;
    gather_acc(img, y0,       x0,       (1.f - wx) * (1.f - wy), r);
    gather_acc(img, y0,       x0 + 1.f, wx         * (1.f - wy), r);
    gather_acc(img, y0 + 1.f, x0,       (1.f - wx) * wy,         r);
    gather_acc(img, y0 + 1.f, x0 + 1.f, wx         * wy,         r);
    return r;   // affine: no clip
}

// layer-0 intermediate at integer pixel (x,y)
__device__ __forceinline__ F3 eval0(const float* __restrict__ img,
                                    const LayerP& P, int x, int y)
{
    if (P.op < 5) return bilin(img, P, x, y);
    const float* p = img + ((size_t)y * IMG_W + x) * 3;
    F3 r;
    float v0 = p[0], v1 = p[1], v2 = p[2];
    if (P.op == 5) {
        r.x = P.f * v0; r.y = P.f * v1; r.z = P.f * v2;
    } else if (P.op == 6) {
        r.x = P.m + P.f * (v0 - P.m);
        r.y = P.m + P.f * (v1 - P.m);
        r.z = P.m + P.f * (v2 - P.m);
    } else {
        float s0 = 0.f, s1 = 0.f, s2 = 0.f;
        #pragma unroll
        for (int dy = -1; dy <= 1; dy++) {
            int yy = min(max(y + dy, 0), IMG_H - 1);
            #pragma unroll
            for (int dx = -1; dx <= 1; dx++) {
                int xx = min(max(x + dx, 0), IMG_W - 1);
                float k = (dx == 0 && dy == 0) ? (5.0f/13.0f) : (1.0f/13.0f);
                const float* q = img + ((size_t)yy * IMG_W + xx) * 3;
                s0 += k * q[0]; s1 += k * q[1]; s2 += k * q[2];
            }
        }
        r.x = s0 + P.f * (v0 - s0);
        r.y = s1 + P.f * (v1 - s1);
        r.z = s2 + P.f * (v2 - s2);
    }
    r.x = fminf(fmaxf(r.x, 0.f), 1.f);
    r.y = fminf(fmaxf(r.y, 0.f), 1.f);
    r.z = fminf(fmaxf(r.z, 0.f), 1.f);
    return r;
}

// ---------------------------------------------------------------------------
// reduce0: mean of original, only for op0 == contrast
// ---------------------------------------------------------------------------
__global__ void reduce0_kernel(const float* __restrict__ in,
                               const int* __restrict__ op_ids)
{
    int b = blockIdx.y;
    if (op_ids[b * 2] != 6) return;
    const float4* img = (const float4*)(in + (size_t)b * NPEL);
    float s = 0.f;
    for (int i = blockIdx.x * 256 + threadIdx.x; i < NPEL / 4; i += RBLK * 256) {
        float4 v = img[i];
        s += v.x + v.y + v.z + v.w;
    }
    __shared__ float sd[256];
    sd[threadIdx.x] = s;
    __syncthreads();
    #pragma unroll
    for (int st = 128; st > 0; st >>= 1) {
        if (threadIdx.x < st) sd[threadIdx.x] += sd[threadIdx.x + st];
        __syncthreads();
    }
    if (threadIdx.x == 0) g_partial0[b * RBLK + blockIdx.x] = sd[0];
}

__global__ void finalize0_kernel(const int* __restrict__ op_ids)
{
    int b = threadIdx.x;
    if (b >= NB || op_ids[b * 2] != 6) return;
    float s = 0.f;
    #pragma unroll
    for (int i = 0; i < RBLK; i++) s += g_partial0[b * RBLK + i];
    g_mean0[b] = s * (1.0f / (float)NPEL);
}

// ---------------------------------------------------------------------------
// reduce1: mean of the virtual intermediate (recomputed), only op1 == contrast
// ---------------------------------------------------------------------------
__global__ void reduce1_kernel(const float* __restrict__ in,
                               const int* __restrict__ op_ids,
                               const int* __restrict__ signs)
{
    int b = blockIdx.y;
    if (op_ids[b * 2 + 1] != 6) return;
    LayerP P0;
    setup_params(P0, op_ids[b * 2], signs[b * 2] ? 1.f : -1.f, g_mean0[b]);
    const float* img = in + (size_t)b * NPEL;
    float s = 0.f;
    for (int i = blockIdx.x * 256 + threadIdx.x; i < NPIX; i += RBLK * 256) {
        F3 v = eval0(img, P0, i & (IMG_W - 1), i >> 9);
        s += v.x + v.y + v.z;
    }
    __shared__ float sd[256];
    sd[threadIdx.x] = s;
    __syncthreads();
    #pragma unroll
    for (int st = 128; st > 0; st >>= 1) {
        if (threadIdx.x < st) sd[threadIdx.x] += sd[threadIdx.x + st];
        __syncthreads();
    }
    if (threadIdx.x == 0) g_partial1[b * RBLK + blockIdx.x] = sd[0];
}

__global__ void finalize1_kernel(const int* __restrict__ op_ids)
{
    int b = threadIdx.x;
    if (b >= NB || op_ids[b * 2 + 1] != 6) return;
    float s = 0.f;
    #pragma unroll
    for (int i = 0; i < RBLK; i++) s += g_partial1[b * RBLK + i];
    g_mean1[b] = s * (1.0f / (float)NPEL);
}

// ---------------------------------------------------------------------------
// Fusion rule: fuse unless BOTH layers are gather-heavy (affine or sharpness).
// ---------------------------------------------------------------------------
__device__ __forceinline__ bool is_fused(int op0, int op1)
{
    bool pw0 = (op0 == 5) || (op0 == 6);
    bool pw1 = (op1 == 5) || (op1 == 6);
    return pw0 || pw1;
}

// ---------------------------------------------------------------------------
// pass1: one thread = one pixel.
//  - fused images: compute FINAL value, write to out.
//  - heavy∘heavy images: compute layer-0 intermediate, write to scratch.
// ---------------------------------------------------------------------------
__global__ void pass1_kernel(const float* __restrict__ in,
                             float* __restrict__ out,
                             const int* __restrict__ op_ids,
                             const int* __restrict__ signs)
{
    const int b   = blockIdx.z;
    const int idx = blockIdx.x * blockDim.x + threadIdx.x;
    const int y   = idx >> 9;
    const int x   = idx & (IMG_W - 1);

    const float* img = in + (size_t)b * NPEL;
    const int op0 = op_ids[b * 2], op1 = op_ids[b * 2 + 1];
    const float s0 = signs[b * 2]     ? 1.f : -1.f;
    const float s1 = signs[b * 2 + 1] ? 1.f : -1.f;

    LayerP P0;
    setup_params(P0, op0, s0, g_mean0[b]);

    F3 r;
    if (!is_fused(op0, op1)) {
        r = eval0(img, P0, x, y);                       // -> scratch
        float* o = g_scratch + (size_t)b * NPEL + (size_t)idx * 3;
        o[0] = r.x; o[1] = r.y; o[2] = r.z;
        return;
    }

    const float f1 = (s1 > 0.f) ? 1.45f : (1.0f / 1.45f);

    if (op1 == 5) {                                     // brightness(last)
        F3 v = eval0(img, P0, x, y);
        r.x = fminf(fmaxf(f1 * v.x, 0.f), 1.f);
        r.y = fminf(fmaxf(f1 * v.y, 0.f), 1.f);
        r.z = fminf(fmaxf(f1 * v.z, 0.f), 1.f);
    } else if (op1 == 6) {                              // contrast(last)
        F3 v = eval0(img, P0, x, y);
        float m = g_mean1[b];
        r.x = fminf(fmaxf(m + f1 * (v.x - m), 0.f), 1.f);
        r.y = fminf(fmaxf(m + f1 * (v.y - m), 0.f), 1.f);
        r.z = fminf(fmaxf(m + f1 * (v.z - m), 0.f), 1.f);
    } else if (op1 < 5) {
        // op1 affine, op0 pointwise (guaranteed by fusion rule):
        // 4 corner taps of the cheap pointwise intermediate
        LayerP P1; setup_params(P1, op1, s1, 0.f);
        const float cx = (IMG_W - 1) * 0.5f, cy = (IMG_H - 1) * 0.5f;
        float xf = (float)x - cx, yf = (float)y - cy;
        float xi = P1.a * xf + P1.b * yf + P1.tx + cx;
        float yi = P1.c * xf + P1.d * yf + P1.ty + cy;
        float x0 = floorf(xi), y0 = floorf(yi);
        float wx = xi - x0,    wy = yi - y0;
        float w[4]  = { (1.f-wx)*(1.f-wy), wx*(1.f-wy), (1.f-wx)*wy, wx*wy };
        float qx[4] = { x0, x0 + 1.f, x0,       x0 + 1.f };
        float qy[4] = { y0, y0,       y0 + 1.f, y0 + 1.f };
        r.x = r.y = r.z = 0.f;
        #pragma unroll
        for (int i = 0; i < 4; i++) {
            bool valid = (qx[i] >= 0.f) && (qx[i] <= (float)(IMG_W - 1)) &&
                         (qy[i] >= 0.f) && (qy[i] <= (float)(IMG_H - 1));
            if (valid) {
                F3 v = eval0(img, P0, (int)qx[i], (int)qy[i]);
                r.x += w[i] * v.x; r.y += w[i] * v.y; r.z += w[i] * v.z;
            } else {
                float f = w[i] * 0.5f;
                r.x += f; r.y += f; r.z += f;
            }
        }
        // affine: no clip
    } else {
        // op1 sharpness, op0 pointwise: 9 cheap taps
        F3 sm = {0.f, 0.f, 0.f}, ctr = {0.f, 0.f, 0.f};
        #pragma unroll
        for (int dy = -1; dy <= 1; dy++) {
            int yy = min(max(y + dy, 0), IMG_H - 1);
            #pragma unroll
            for (int dx = -1; dx <= 1; dx++) {
                int xx = min(max(x + dx, 0), IMG_W - 1);
                float k = (dx == 0 && dy == 0) ? (5.0f/13.0f) : (1.0f/13.0f);
                F3 v = eval0(img, P0, xx, yy);
                if (dx == 0 && dy == 0) ctr = v;
                sm.x += k * v.x; sm.y += k * v.y; sm.z += k * v.z;
            }
        }
        r.x = fminf(fmaxf(sm.x + f1 * (ctr.x - sm.x), 0.f), 1.f);
        r.y = fminf(fmaxf(sm.y + f1 * (ctr.y - sm.y), 0.f), 1.f);
        r.z = fminf(fmaxf(sm.z + f1 * (ctr.z - sm.z), 0.f), 1.f);
    }

    float* o = out + (size_t)b * NPEL + (size_t)idx * 3;
    o[0] = r.x; o[1] = r.y; o[2] = r.z;
}

// ---------------------------------------------------------------------------
// pass2: heavy∘heavy images only — layer 1 (affine or sharpness) from scratch
// ---------------------------------------------------------------------------
__global__ void pass2_kernel(float* __restrict__ out,
                             const int* __restrict__ op_ids,
                             const int* __restrict__ signs)
{
    const int b   = blockIdx.z;
    const int op0 = op_ids[b * 2], op1 = op_ids[b * 2 + 1];
    if (is_fused(op0, op1)) return;

    const int idx = blockIdx.x * blockDim.x + threadIdx.x;
    const int y   = idx >> 9;
    const int x   = idx & (IMG_W - 1);

    const float* img = g_scratch + (size_t)b * NPEL;
    const float s1 = signs[b * 2 + 1] ? 1.f : -1.f;

    LayerP P1;
    setup_params(P1, op1, s1, 0.f);     // op1 is affine or sharpness here

    F3 r = eval0(img, P1, x, y);

    float* o = out + (size_t)b * NPEL + (size_t)idx * 3;
    o[0] = r.x; o[1] = r.y; o[2] = r.z;
}

// ---------------------------------------------------------------------------
extern "C" void kernel_launch(void* const* d_in, const int* in_sizes, int n_in,
                              void* d_out, int out_size)
{
    const float* images = (const float*)d_in[0];
    const int*   op_ids = (const int*)  d_in[1];
    const int*   signs  = (const int*)  d_in[2];
    float*       out    = (float*)d_out;

    dim3 rgrid(RBLK, NB);
    dim3 agrid(NPIX / 256, 1, NB);

    reduce0_kernel  <<<rgrid, 256>>>(images, op_ids);
    finalize0_kernel<<<1, 64>>>(op_ids);
    reduce1_kernel  <<<rgrid, 256>>>(images, op_ids, signs);
    finalize1_kernel<<<1, 64>>>(op_ids);
    pass1_kernel    <<<agrid, 256>>>(images, out, op_ids, signs);
    pass2_kernel    <<<agrid, 256>>>(out, op_ids, signs);
}

// round 6
// speedup vs baseline: 2.5947x; 1.1925x over previous
#include <cuda_runtime.h>
#include <math.h>

#define IMG_H 512
#define IMG_W 512
#define NB    64
#define NPIX  (IMG_H * IMG_W)
#define NPEL  (NPIX * 3)
#define RBLK  32

__device__ float g_scratch[(size_t)NB * NPEL];
__device__ float g_partial0[NB * RBLK];
__device__ float g_partial1[NB * RBLK];

struct F3 { float x, y, z; };

struct LayerP {
    int   op;
    float f;
    float a, b, tx, c, d, ty;
};

__device__ __forceinline__ void setup_params(LayerP& P, int op, float s)
{
    P.op = op;
    P.a = 1.f; P.b = 0.f; P.tx = 0.f; P.c = 0.f; P.d = 1.f; P.ty = 0.f;
    if (op == 0) {                          // rotate s*15deg
        float th = s * 0.2617993877991494f;
        P.a = cosf(th); P.b = sinf(th); P.c = -P.b; P.d = P.a;
    } else if (op == 1) { P.b  = -s * 0.15f; }
    else if (op == 2)   { P.c  = -s * 0.15f; }
    else if (op == 3)   { P.tx = -s * 0.15f * (float)IMG_W; }
    else if (op == 4)   { P.ty = -s * 0.15f * (float)IMG_H; }
    P.f = (s > 0.f) ? 1.45f : (1.0f / 1.45f);   // ENH = 1 + 0.9*0.5
}

// inline deterministic partial-sum -> mean (all threads compute, broadcast loads)
__device__ __forceinline__ float inline_mean(const float* __restrict__ part, int b)
{
    float s = 0.f;
    #pragma unroll
    for (int i = 0; i < RBLK; i++) s += part[b * RBLK + i];
    return s * (1.0f / (float)NPEL);
}

__device__ __forceinline__ void gather_acc(const float* __restrict__ img,
                                           float yy, float xx, float w, F3& r)
{
    bool valid = (xx >= 0.f) && (xx <= (float)(IMG_W - 1)) &&
                 (yy >= 0.f) && (yy <= (float)(IMG_H - 1));
    int xc = (int)fminf(fmaxf(xx, 0.f), (float)(IMG_W - 1));
    int yc = (int)fminf(fmaxf(yy, 0.f), (float)(IMG_H - 1));
    const float* p = img + ((size_t)yc * IMG_W + xc) * 3;
    if (valid) { r.x += w * p[0]; r.y += w * p[1]; r.z += w * p[2]; }
    else       { float f = w * 0.5f; r.x += f; r.y += f; r.z += f; }
}

__device__ __forceinline__ F3 bilin(const float* __restrict__ img,
                                    const LayerP& P, int x, int y)
{
    const float cx = (IMG_W - 1) * 0.5f, cy = (IMG_H - 1) * 0.5f;
    float xf = (float)x - cx, yf = (float)y - cy;
    float xi = P.a * xf + P.b * yf + P.tx + cx;
    float yi = P.c * xf + P.d * yf + P.ty + cy;
    float x0 = floorf(xi), y0 = floorf(yi);
    float wx = xi - x0,    wy = yi - y0;
    F3 r; r.x = r.y = r.z = 0.f;
    gather_acc(img, y0,       x0,       (1.f - wx) * (1.f - wy), r);
    gather_acc(img, y0,       x0 + 1.f, wx         * (1.f - wy), r);
    gather_acc(img, y0 + 1.f, x0,       (1.f - wx) * wy,         r);
    gather_acc(img, y0 + 1.f, x0 + 1.f, wx         * wy,         r);
    return r;   // affine: no clip
}

__device__ __forceinline__ F3 sharp3x3(const float* __restrict__ img,
                                       float f, int x, int y)
{
    const float* p = img + ((size_t)y * IMG_W + x) * 3;
    float v0 = p[0], v1 = p[1], v2 = p[2];
    float s0 = 0.f, s1 = 0.f, s2 = 0.f;
    #pragma unroll
    for (int dy = -1; dy <= 1; dy++) {
        int yy = min(max(y + dy, 0), IMG_H - 1);
        #pragma unroll
        for (int dx = -1; dx <= 1; dx++) {
            int xx = min(max(x + dx, 0), IMG_W - 1);
            float k = (dx == 0 && dy == 0) ? (5.0f/13.0f) : (1.0f/13.0f);
            const float* q = img + ((size_t)yy * IMG_W + xx) * 3;
            s0 += k * q[0]; s1 += k * q[1]; s2 += k * q[2];
        }
    }
    F3 r;
    r.x = fminf(fmaxf(s0 + f * (v0 - s0), 0.f), 1.f);
    r.y = fminf(fmaxf(s1 + f * (v1 - s1), 0.f), 1.f);
    r.z = fminf(fmaxf(s2 + f * (v2 - s2), 0.f), 1.f);
    return r;
}

// ---------------------------------------------------------------------------
// reduce0: per-image sum of original (only op0 == contrast), float4 streaming
// ---------------------------------------------------------------------------
__global__ void reduce0_kernel(const float* __restrict__ in,
                               const int* __restrict__ op_ids)
{
    int b = blockIdx.y;
    if (op_ids[b * 2] != 6) return;
    const float4* img = (const float4*)(in + (size_t)b * NPEL);
    float s = 0.f;
    for (int i = blockIdx.x * 256 + threadIdx.x; i < NPEL / 4; i += RBLK * 256) {
        float4 v = img[i];
        s += v.x + v.y + v.z + v.w;
    }
    __shared__ float sd[256];
    sd[threadIdx.x] = s;
    __syncthreads();
    #pragma unroll
    for (int st = 128; st > 0; st >>= 1) {
        if (threadIdx.x < st) sd[threadIdx.x] += sd[threadIdx.x + st];
        __syncthreads();
    }
    if (threadIdx.x == 0) g_partial0[b * RBLK + blockIdx.x] = sd[0];
}

// ---------------------------------------------------------------------------
// reduce1: per-image sum of the materialized intermediate in scratch
// (only op1 == contrast; those images always take the scratch path)
// ---------------------------------------------------------------------------
__global__ void reduce1_kernel(const int* __restrict__ op_ids)
{
    int b = blockIdx.y;
    if (op_ids[b * 2 + 1] != 6) return;
    const float4* img = (const float4*)(g_scratch + (size_t)b * NPEL);
    float s = 0.f;
    for (int i = blockIdx.x * 256 + threadIdx.x; i < NPEL / 4; i += RBLK * 256) {
        float4 v = img[i];
        s += v.x + v.y + v.z + v.w;
    }
    __shared__ float sd[256];
    sd[threadIdx.x] = s;
    __syncthreads();
    #pragma unroll
    for (int st = 128; st > 0; st >>= 1) {
        if (threadIdx.x < st) sd[threadIdx.x] += sd[threadIdx.x + st];
        __syncthreads();
    }
    if (threadIdx.x == 0) g_partial1[b * RBLK + blockIdx.x] = sd[0];
}

// ---------------------------------------------------------------------------
// pass1: layer 0 for all images (thread = pixel, lean).
// If op1 == brightness, apply it inline and write final -> out.
// Otherwise write the intermediate -> scratch.
// ---------------------------------------------------------------------------
__global__ void pass1_kernel(const float* __restrict__ in,
                             float* __restrict__ out,
                             const int* __restrict__ op_ids,
                             const int* __restrict__ signs)
{
    const int b   = blockIdx.z;
    const int idx = blockIdx.x * blockDim.x + threadIdx.x;

    const int op0 = op_ids[b * 2], op1 = op_ids[b * 2 + 1];
    const float s0 = signs[b * 2]     ? 1.f : -1.f;
    const float s1 = signs[b * 2 + 1] ? 1.f : -1.f;
    const bool  fuse_b = (op1 == 5);
    const float f1 = (s1 > 0.f) ? 1.45f : (1.0f / 1.45f);

    const float* img = in + (size_t)b * NPEL;
    float* dstbase = (fuse_b ? out : g_scratch) + (size_t)b * NPEL;

    // ---- vector fast path for pointwise op0 (uniform per image) ----
    if (op0 == 5 || op0 == 6) {
        if (idx >= NPEL / 4) return;
        const float f0 = (s0 > 0.f) ? 1.45f : (1.0f / 1.45f);
        float4 v = ((const float4*)img)[idx];
        float t[4] = { v.x, v.y, v.z, v.w };
        if (op0 == 5) {
            #pragma unroll
            for (int k = 0; k < 4; k++)
                t[k] = fminf(fmaxf(f0 * t[k], 0.f), 1.f);
        } else {
            const float m = inline_mean(g_partial0, b);
            #pragma unroll
            for (int k = 0; k < 4; k++)
                t[k] = fminf(fmaxf(m + f0 * (t[k] - m), 0.f), 1.f);
        }
        if (fuse_b) {
            #pragma unroll
            for (int k = 0; k < 4; k++)
                t[k] = fminf(fmaxf(f1 * t[k], 0.f), 1.f);
        }
        ((float4*)dstbase)[idx] = make_float4(t[0], t[1], t[2], t[3]);
        return;
    }

    // ---- pixel path: affine or sharpness ----
    const int y = idx >> 9;
    const int x = idx & (IMG_W - 1);

    LayerP P0;
    setup_params(P0, op0, s0);

    F3 r = (op0 < 5) ? bilin(img, P0, x, y) : sharp3x3(img, P0.f, x, y);

    if (fuse_b) {
        r.x = fminf(fmaxf(f1 * r.x, 0.f), 1.f);
        r.y = fminf(fmaxf(f1 * r.y, 0.f), 1.f);
        r.z = fminf(fmaxf(f1 * r.z, 0.f), 1.f);
    }

    float* o = dstbase + (size_t)idx * 3;
    o[0] = r.x; o[1] = r.y; o[2] = r.z;
}

// ---------------------------------------------------------------------------
// pass2: layer 1 from scratch -> out. op1==brightness already done in pass1.
// ---------------------------------------------------------------------------
__global__ void pass2_kernel(float* __restrict__ out,
                             const int* __restrict__ op_ids,
                             const int* __restrict__ signs)
{
    const int b   = blockIdx.z;
    const int op1 = op_ids[b * 2 + 1];
    if (op1 == 5) return;                   // fused into pass1

    const int idx = blockIdx.x * blockDim.x + threadIdx.x;
    const float s1 = signs[b * 2 + 1] ? 1.f : -1.f;
    const float f1 = (s1 > 0.f) ? 1.45f : (1.0f / 1.45f);

    const float* img = g_scratch + (size_t)b * NPEL;
    float* outb = out + (size_t)b * NPEL;

    if (op1 == 6) {                         // contrast: vector streaming
        if (idx >= NPEL / 4) return;
        const float m = inline_mean(g_partial1, b);
        float4 v = ((const float4*)img)[idx];
        float t[4] = { v.x, v.y, v.z, v.w };
        #pragma unroll
        for (int k = 0; k < 4; k++)
            t[k] = fminf(fmaxf(m + f1 * (t[k] - m), 0.f), 1.f);
        ((float4*)outb)[idx] = make_float4(t[0], t[1], t[2], t[3]);
        return;
    }

    const int y = idx >> 9;
    const int x = idx & (IMG_W - 1);

    LayerP P1;
    setup_params(P1, op1, s1);

    F3 r = (op1 < 5) ? bilin(img, P1, x, y) : sharp3x3(img, f1, x, y);

    float* o = outb + (size_t)idx * 3;
    o[0] = r.x; o[1] = r.y; o[2] = r.z;
}

// ---------------------------------------------------------------------------
extern "C" void kernel_launch(void* const* d_in, const int* in_sizes, int n_in,
                              void* d_out, int out_size)
{
    const float* images = (const float*)d_in[0];
    const int*   op_ids = (const int*)  d_in[1];
    const int*   signs  = (const int*)  d_in[2];
    float*       out    = (float*)d_out;

    dim3 rgrid(RBLK, NB);
    dim3 agrid(NPIX / 256, 1, NB);

    reduce0_kernel<<<rgrid, 256>>>(images, op_ids);
    pass1_kernel  <<<agrid, 256>>>(images, out, op_ids, signs);
    reduce1_kernel<<<rgrid, 256>>>(op_ids);
    pass2_kernel  <<<agrid, 256>>>(out, op_ids, signs);
}

// round 7
// speedup vs baseline: 2.7808x; 1.0718x over previous
#include <cuda_runtime.h>
#include <math.h>

#define IMG_H 512
#define IMG_W 512
#define NB    64
#define NPIX  (IMG_H * IMG_W)
#define NPEL  (NPIX * 3)
#define RBLK  32
#define ROWF  (IMG_W * 3)

__device__ float g_scratch[(size_t)NB * NPEL];
__device__ float g_partial0[NB * RBLK];
__device__ float g_partial1[NB * RBLK];

struct F3 { float x, y, z; };

__device__ __forceinline__ float inline_mean(const float* __restrict__ part, int b)
{
    float s = 0.f;
    #pragma unroll
    for (int i = 0; i < RBLK; i++) s += part[b * RBLK + i];
    return s * (1.0f / (float)NPEL);
}

// ---------------------------------------------------------------------------
// horizontal 2-tap bilinear (wy == 0 exactly): taps (y, x0), (y, x0+1)
// ---------------------------------------------------------------------------
__device__ __forceinline__ F3 bilin_h(const float* __restrict__ img, float xi, int y)
{
    float x0f = floorf(xi);
    float wx  = xi - x0f;
    float w0  = 1.f - wx;
    int   x0  = (int)x0f;
    const float* row = img + (size_t)y * ROWF;
    F3 r;
    if (x0 >= 0 && x0 < IMG_W - 1) {                 // interior fast path
        const float* p = row + x0 * 3;
        r.x = w0 * p[0] + wx * p[3];
        r.y = w0 * p[1] + wx * p[4];
        r.z = w0 * p[2] + wx * p[5];
    } else {
        bool v0 = (x0 >= 0)  && (x0 <= IMG_W - 1);
        bool v1 = (x0 >= -1) && (x0 <= IMG_W - 2);
        int xc0 = min(max(x0,     0), IMG_W - 1);
        int xc1 = min(max(x0 + 1, 0), IMG_W - 1);
        const float* p0 = row + xc0 * 3;
        const float* p1 = row + xc1 * 3;
        float a0 = v0 ? p0[0] : 0.5f, a1 = v0 ? p0[1] : 0.5f, a2 = v0 ? p0[2] : 0.5f;
        float b0 = v1 ? p1[0] : 0.5f, b1 = v1 ? p1[1] : 0.5f, b2 = v1 ? p1[2] : 0.5f;
        r.x = w0 * a0 + wx * b0;
        r.y = w0 * a1 + wx * b1;
        r.z = w0 * a2 + wx * b2;
    }
    return r;
}

// ---------------------------------------------------------------------------
// vertical 2-tap bilinear (wx == 0 exactly): taps (y0, x), (y0+1, x)
// ---------------------------------------------------------------------------
__device__ __forceinline__ F3 bilin_v(const float* __restrict__ img, float yi, int x)
{
    float y0f = floorf(yi);
    float wy  = yi - y0f;
    float w0  = 1.f - wy;
    int   y0  = (int)y0f;
    F3 r;
    if (y0 >= 0 && y0 < IMG_H - 1) {                 // interior fast path
        const float* p = img + ((size_t)y0 * IMG_W + x) * 3;
        const float* q = p + ROWF;
        r.x = w0 * p[0] + wy * q[0];
        r.y = w0 * p[1] + wy * q[1];
        r.z = w0 * p[2] + wy * q[2];
    } else {
        bool v0 = (y0 >= 0)  && (y0 <= IMG_H - 1);
        bool v1 = (y0 >= -1) && (y0 <= IMG_H - 2);
        int yc0 = min(max(y0,     0), IMG_H - 1);
        int yc1 = min(max(y0 + 1, 0), IMG_H - 1);
        const float* p0 = img + ((size_t)yc0 * IMG_W + x) * 3;
        const float* p1 = img + ((size_t)yc1 * IMG_W + x) * 3;
        float a0 = v0 ? p0[0] : 0.5f, a1 = v0 ? p0[1] : 0.5f, a2 = v0 ? p0[2] : 0.5f;
        float b0 = v1 ? p1[0] : 0.5f, b1 = v1 ? p1[1] : 0.5f, b2 = v1 ? p1[2] : 0.5f;
        r.x = w0 * a0 + wy * b0;
        r.y = w0 * a1 + wy * b1;
        r.z = w0 * a2 + wy * b2;
    }
    return r;
}

// ---------------------------------------------------------------------------
// general 4-tap bilinear (rotate only)
// ---------------------------------------------------------------------------
__device__ __forceinline__ F3 bilin4(const float* __restrict__ img, float xi, float yi)
{
    float x0f = floorf(xi), y0f = floorf(yi);
    float wx = xi - x0f,    wy = yi - y0f;
    int   x0 = (int)x0f,    y0 = (int)y0f;
    float w00 = (1.f - wx) * (1.f - wy);
    float w10 = wx * (1.f - wy);
    float w01 = (1.f - wx) * wy;
    float w11 = wx * wy;
    F3 r;
    if (x0 >= 0 && x0 < IMG_W - 1 && y0 >= 0 && y0 < IMG_H - 1) {
        const float* p = img + ((size_t)y0 * IMG_W + x0) * 3;
        const float* q = p + ROWF;
        r.x = w00 * p[0] + w10 * p[3] + w01 * q[0] + w11 * q[3];
        r.y = w00 * p[1] + w10 * p[4] + w01 * q[1] + w11 * q[4];
        r.z = w00 * p[2] + w10 * p[5] + w01 * q[2] + w11 * q[5];
    } else {
        bool vx0 = (x0 >= 0)  && (x0 <= IMG_W - 1);
        bool vx1 = (x0 >= -1) && (x0 <= IMG_W - 2);
        bool vy0 = (y0 >= 0)  && (y0 <= IMG_H - 1);
        bool vy1 = (y0 >= -1) && (y0 <= IMG_H - 2);
        int xc0 = min(max(x0,     0), IMG_W - 1);
        int xc1 = min(max(x0 + 1, 0), IMG_W - 1);
        int yc0 = min(max(y0,     0), IMG_H - 1);
        int yc1 = min(max(y0 + 1, 0), IMG_H - 1);
        const float* p00 = img + ((size_t)yc0 * IMG_W + xc0) * 3;
        const float* p10 = img + ((size_t)yc0 * IMG_W + xc1) * 3;
        const float* p01 = img + ((size_t)yc1 * IMG_W + xc0) * 3;
        const float* p11 = img + ((size_t)yc1 * IMG_W + xc1) * 3;
        bool v00 = vx0 && vy0, v10 = vx1 && vy0, v01 = vx0 && vy1, v11 = vx1 && vy1;
        r.x = w00 * (v00 ? p00[0] : 0.5f) + w10 * (v10 ? p10[0] : 0.5f)
            + w01 * (v01 ? p01[0] : 0.5f) + w11 * (v11 ? p11[0] : 0.5f);
        r.y = w00 * (v00 ? p00[1] : 0.5f) + w10 * (v10 ? p10[1] : 0.5f)
            + w01 * (v01 ? p01[1] : 0.5f) + w11 * (v11 ? p11[1] : 0.5f);
        r.z = w00 * (v00 ? p00[2] : 0.5f) + w10 * (v10 ? p10[2] : 0.5f)
            + w01 * (v01 ? p01[2] : 0.5f) + w11 * (v11 ? p11[2] : 0.5f);
    }
    return r;
}

// ---------------------------------------------------------------------------
// sharpness with interior fast path
// ---------------------------------------------------------------------------
__device__ __forceinline__ F3 sharp3x3(const float* __restrict__ img,
                                       float f, int x, int y)
{
    F3 r;
    if (x >= 1 && x < IMG_W - 1 && y >= 1 && y < IMG_H - 1) {
        const float* pc = img + ((size_t)y * IMG_W + x) * 3;
        const float* pm = pc - ROWF;
        const float* pp = pc + ROWF;
        float v0 = pc[0], v1 = pc[1], v2 = pc[2];
        float s0 = pm[-3] + pm[0] + pm[3] + pc[-3] + pc[3] + pp[-3] + pp[0] + pp[3];
        float s1 = pm[-2] + pm[1] + pm[4] + pc[-2] + pc[4] + pp[-2] + pp[1] + pp[4];
        float s2 = pm[-1] + pm[2] + pm[5] + pc[-1] + pc[5] + pp[-1] + pp[2] + pp[5];
        s0 = (s0 + 5.f * v0) * (1.f / 13.f);
        s1 = (s1 + 5.f * v1) * (1.f / 13.f);
        s2 = (s2 + 5.f * v2) * (1.f / 13.f);
        r.x = fminf(fmaxf(s0 + f * (v0 - s0), 0.f), 1.f);
        r.y = fminf(fmaxf(s1 + f * (v1 - s1), 0.f), 1.f);
        r.z = fminf(fmaxf(s2 + f * (v2 - s2), 0.f), 1.f);
    } else {
        const float* p = img + ((size_t)y * IMG_W + x) * 3;
        float v0 = p[0], v1 = p[1], v2 = p[2];
        float s0 = 0.f, s1 = 0.f, s2 = 0.f;
        #pragma unroll
        for (int dy = -1; dy <= 1; dy++) {
            int yy = min(max(y + dy, 0), IMG_H - 1);
            #pragma unroll
            for (int dx = -1; dx <= 1; dx++) {
                int xx = min(max(x + dx, 0), IMG_W - 1);
                float k = (dx == 0 && dy == 0) ? (5.0f/13.0f) : (1.0f/13.0f);
                const float* q = img + ((size_t)yy * IMG_W + xx) * 3;
                s0 += k * q[0]; s1 += k * q[1]; s2 += k * q[2];
            }
        }
        r.x = fminf(fmaxf(s0 + f * (v0 - s0), 0.f), 1.f);
        r.y = fminf(fmaxf(s1 + f * (v1 - s1), 0.f), 1.f);
        r.z = fminf(fmaxf(s2 + f * (v2 - s2), 0.f), 1.f);
    }
    return r;
}

// ---------------------------------------------------------------------------
// gather-family dispatch (op in {0..4, 7}); op is image-uniform
// ---------------------------------------------------------------------------
__device__ __forceinline__ F3 apply_gather(const float* __restrict__ img,
                                           int op, float s, int x, int y)
{
    const float cx = (IMG_W - 1) * 0.5f, cy = (IMG_H - 1) * 0.5f;
    const float xf = (float)x - cx, yf = (float)y - cy;
    if (op == 0) {                              // rotate
        float th = s * 0.2617993877991494f;
        float co = cosf(th), si = sinf(th);
        return bilin4(img, co * xf + si * yf + cx, -si * xf + co * yf + cy);
    }
    if (op == 1) return bilin_h(img, xf + (-s * 0.15f) * yf + cx, y);           // shear_x
    if (op == 2) return bilin_v(img, yf + (-s * 0.15f) * xf + cy, x);           // shear_y
    if (op == 3) return bilin_h(img, xf + (-s * 0.15f * (float)IMG_W) + cx, y); // trans_x
    if (op == 4) return bilin_v(img, yf + (-s * 0.15f * (float)IMG_H) + cy, x); // trans_y
    float f = (s > 0.f) ? 1.45f : (1.0f / 1.45f);
    return sharp3x3(img, f, x, y);              // sharpness (op 7)
}

// ---------------------------------------------------------------------------
// reduce0: per-image partial sums of original (only op0 == contrast)
// ---------------------------------------------------------------------------
__global__ void reduce0_kernel(const float* __restrict__ in,
                               const int* __restrict__ op_ids)
{
    int b = blockIdx.y;
    if (op_ids[b * 2] != 6) return;
    const float4* img = (const float4*)(in + (size_t)b * NPEL);
    float s = 0.f;
    for (int i = blockIdx.x * 256 + threadIdx.x; i < NPEL / 4; i += RBLK * 256) {
        float4 v = img[i];
        s += v.x + v.y + v.z + v.w;
    }
    __shared__ float sd[256];
    sd[threadIdx.x] = s;
    __syncthreads();
    #pragma unroll
    for (int st = 128; st > 0; st >>= 1) {
        if (threadIdx.x < st) sd[threadIdx.x] += sd[threadIdx.x + st];
        __syncthreads();
    }
    if (threadIdx.x == 0) g_partial0[b * RBLK + blockIdx.x] = sd[0];
}

// ---------------------------------------------------------------------------
// reduce1: partial sums of the materialized intermediate (op1 == contrast)
// ---------------------------------------------------------------------------
__global__ void reduce1_kernel(const int* __restrict__ op_ids)
{
    int b = blockIdx.y;
    if (op_ids[b * 2 + 1] != 6) return;
    const float4* img = (const float4*)(g_scratch + (size_t)b * NPEL);
    float s = 0.f;
    for (int i = blockIdx.x * 256 + threadIdx.x; i < NPEL / 4; i += RBLK * 256) {
        float4 v = img[i];
        s += v.x + v.y + v.z + v.w;
    }
    __shared__ float sd[256];
    sd[threadIdx.x] = s;
    __syncthreads();
    #pragma unroll
    for (int st = 128; st > 0; st >>= 1) {
        if (threadIdx.x < st) sd[threadIdx.x] += sd[threadIdx.x + st];
        __syncthreads();
    }
    if (threadIdx.x == 0) g_partial1[b * RBLK + blockIdx.x] = sd[0];
}

// ---------------------------------------------------------------------------
// pass1: layer 0 (thread = pixel). op1==brightness fused inline -> out,
// else intermediate -> scratch. Pointwise op0 goes float4.
// ---------------------------------------------------------------------------
__global__ void pass1_kernel(const float* __restrict__ in,
                             float* __restrict__ out,
                             const int* __restrict__ op_ids,
                             const int* __restrict__ signs)
{
    const int b   = blockIdx.z;
    const int idx = blockIdx.x * blockDim.x + threadIdx.x;

    const int op0 = op_ids[b * 2], op1 = op_ids[b * 2 + 1];
    const float s0 = signs[b * 2]     ? 1.f : -1.f;
    const float s1 = signs[b * 2 + 1] ? 1.f : -1.f;
    const bool  fuse_b = (op1 == 5);
    const float f1 = (s1 > 0.f) ? 1.45f : (1.0f / 1.45f);

    const float* img = in + (size_t)b * NPEL;
    float* dstbase = (fuse_b ? out : g_scratch) + (size_t)b * NPEL;

    if (op0 == 5 || op0 == 6) {                 // pointwise: float4 streaming
        if (idx >= NPEL / 4) return;
        const float f0 = (s0 > 0.f) ? 1.45f : (1.0f / 1.45f);
        float4 v = ((const float4*)img)[idx];
        float t[4] = { v.x, v.y, v.z, v.w };
        if (op0 == 5) {
            #pragma unroll
            for (int k = 0; k < 4; k++)
                t[k] = fminf(fmaxf(f0 * t[k], 0.f), 1.f);
        } else {
            const float m = inline_mean(g_partial0, b);
            #pragma unroll
            for (int k = 0; k < 4; k++)
                t[k] = fminf(fmaxf(m + f0 * (t[k] - m), 0.f), 1.f);
        }
        if (fuse_b) {
            #pragma unroll
            for (int k = 0; k < 4; k++)
                t[k] = fminf(fmaxf(f1 * t[k], 0.f), 1.f);
        }
        ((float4*)dstbase)[idx] = make_float4(t[0], t[1], t[2], t[3]);
        return;
    }

    const int y = idx >> 9;
    const int x = idx & (IMG_W - 1);

    F3 r = apply_gather(img, op0, s0, x, y);

    if (fuse_b) {
        r.x = fminf(fmaxf(f1 * r.x, 0.f), 1.f);
        r.y = fminf(fmaxf(f1 * r.y, 0.f), 1.f);
        r.z = fminf(fmaxf(f1 * r.z, 0.f), 1.f);
    }

    float* o = dstbase + (size_t)idx * 3;
    o[0] = r.x; o[1] = r.y; o[2] = r.z;
}

// ---------------------------------------------------------------------------
// pass2: layer 1 from scratch -> out (op1==brightness already done)
// ---------------------------------------------------------------------------
__global__ void pass2_kernel(float* __restrict__ out,
                             const int* __restrict__ op_ids,
                             const int* __restrict__ signs)
{
    const int b   = blockIdx.z;
    const int op1 = op_ids[b * 2 + 1];
    if (op1 == 5) return;

    const int idx = blockIdx.x * blockDim.x + threadIdx.x;
    const float s1 = signs[b * 2 + 1] ? 1.f : -1.f;
    const float f1 = (s1 > 0.f) ? 1.45f : (1.0f / 1.45f);

    const float* img = g_scratch + (size_t)b * NPEL;
    float* outb = out + (size_t)b * NPEL;

    if (op1 == 6) {                             // contrast: float4 streaming
        if (idx >= NPEL / 4) return;
        const float m = inline_mean(g_partial1, b);
        float4 v = ((const float4*)img)[idx];
        float t[4] = { v.x, v.y, v.z, v.w };
        #pragma unroll
        for (int k = 0; k < 4; k++)
            t[k] = fminf(fmaxf(m + f1 * (t[k] - m), 0.f), 1.f);
        ((float4*)outb)[idx] = make_float4(t[0], t[1], t[2], t[3]);
        return;
    }

    const int y = idx >> 9;
    const int x = idx & (IMG_W - 1);

    F3 r = apply_gather(img, op1, s1, x, y);

    float* o = outb + (size_t)idx * 3;
    o[0] = r.x; o[1] = r.y; o[2] = r.z;
}

// ---------------------------------------------------------------------------
extern "C" void kernel_launch(void* const* d_in, const int* in_sizes, int n_in,
                              void* d_out, int out_size)
{
    const float* images = (const float*)d_in[0];
    const int*   op_ids = (const int*)  d_in[1];
    const int*   signs  = (const int*)  d_in[2];
    float*       out    = (float*)d_out;

    dim3 rgrid(RBLK, NB);
    dim3 agrid(NPIX / 256, 1, NB);

    reduce0_kernel<<<rgrid, 256>>>(images, op_ids);
    pass1_kernel  <<<agrid, 256>>>(images, out, op_ids, signs);
    reduce1_kernel<<<rgrid, 256>>>(op_ids);
    pass2_kernel  <<<agrid, 256>>>(out, op_ids, signs);
}